// round 5
// baseline (speedup 1.0000x reference)
#include <cuda_runtime.h>
#include <cuda_bf16.h>
#include <math.h>
#include <stdint.h>

// Problem constants
#define NB 2          // batch
#define NC 50         // channels
#define NCR 25        // reduced channels
#define NP 2304       // H*W = 48*48
#define STOT 7470     // total pyramid spatial positions (= L)
#define LPAD 7552     // L padded to multiple of 128
#define KS1 256       // per-section K for GEMM1 (bf16 split)
#define KP1 768       // 3*256, GEMM1 split-K total
#define KP2 22656     // 3*7552, GEMM2 split-K total
#define NV 512        // 450 value dims padded to 512

__constant__ int c_n[5]   = {48, 43, 38, 33, 28};
__constant__ int c_off[5] = {0, 2304, 4153, 5597, 6686};

// ---- scratch (static __device__ arrays; no allocations) ----
__device__ float g_ref [(size_t)NB * NC  * STOT];
__device__ float g_mb  [(size_t)NB * NCR * NP];
__device__ float g_mall[(size_t)NB * NCR * STOT];
__device__ float g_ball[(size_t)NB * NC  * STOT];
__device__ float g_sc  [(size_t)NB * NP * LPAD];          // scores (pre-softmax)
__device__ float g_O   [(size_t)NB * NP * NV];            // (attn @ values), normalized
__device__ float g_isum[(size_t)NB * NP];                 // 1/softmax-denominator
__device__ __align__(256) __nv_bfloat16 g_xqs  [(size_t)NB * NP * KP1];   // A1 (hi,lo,hi)
__device__ __align__(256) __nv_bfloat16 g_wns  [(size_t)NB * LPAD * KP1]; // B1 (hi,hi,lo)
__device__ __align__(256) __nv_bfloat16 g_attns[(size_t)NB * NP * KP2];   // A2 (hi,lo,hi)
__device__ __align__(256) __nv_bfloat16 g_rawTs[(size_t)NB * NV * KP2];   // B2 (hi,hi,lo)

// ===========================================================================
// PTX helpers
// ===========================================================================
__device__ __forceinline__ uint32_t smem_u32(const void* p)
{
    uint32_t a;
    asm("{ .reg .u64 t; cvta.to.shared.u64 t, %1; cvt.u32.u64 %0, t; }" : "=r"(a) : "l"(p));
    return a;
}
__device__ __forceinline__ void cpa16(uint32_t dst, const void* src)
{
    asm volatile("cp.async.cg.shared.global [%0], [%1], 16;" :: "r"(dst), "l"(src));
}
__device__ __forceinline__ void cpa_commit() { asm volatile("cp.async.commit_group;" ::: "memory"); }
template <int N> __device__ __forceinline__ void cpa_wait()
{
    asm volatile("cp.async.wait_group %0;" :: "n"(N) : "memory");
}
__device__ __forceinline__ void ldm_x4(uint32_t& r0, uint32_t& r1, uint32_t& r2, uint32_t& r3,
                                       uint32_t addr)
{
    asm volatile("ldmatrix.sync.aligned.m8n8.x4.shared.b16 {%0,%1,%2,%3}, [%4];"
                 : "=r"(r0), "=r"(r1), "=r"(r2), "=r"(r3) : "r"(addr));
}
__device__ __forceinline__ void mma16816(float* d, const uint32_t* a, const uint32_t* b)
{
    asm volatile("mma.sync.aligned.m16n8k16.row.col.f32.bf16.bf16.f32 "
                 "{%0,%1,%2,%3}, {%4,%5,%6,%7}, {%8,%9}, {%0,%1,%2,%3};"
                 : "+f"(d[0]), "+f"(d[1]), "+f"(d[2]), "+f"(d[3])
                 : "r"(a[0]), "r"(a[1]), "r"(a[2]), "r"(a[3]), "r"(b[0]), "r"(b[1]));
}
__device__ __forceinline__ uint32_t swz(uint32_t off) { return off ^ ((off >> 3) & 0x70); }

__device__ __forceinline__ void split2(float v, __nv_bfloat16& h, __nv_bfloat16& l)
{
    h = __float2bfloat16(v);
    l = __float2bfloat16(v - __bfloat162float(h));
}

__device__ __forceinline__ int scale_of(int l)
{
    int s = 4;
    while (s > 0 && l < c_off[s]) s--;
    return s;
}

// ===========================================================================
// fused conv1x1 (+PReLU): computes C1 (+optionally C2) output channel groups
// in one pass. x kept in registers (50 loads per thread, reused for ALL oc).
// ===========================================================================
__global__ void k_convs(const float* __restrict__ in,
                        const float* __restrict__ W1, const float* __restrict__ B1,
                        const float* __restrict__ A1,
                        const float* __restrict__ W2, const float* __restrict__ B2,
                        const float* __restrict__ A2,
                        float* __restrict__ out1, int C1,
                        float* __restrict__ out2, int C2, int S)
{
    __shared__ float w[75 * 52];        // rows padded to 52 floats (16B-aligned)
    __shared__ float bias[75];
    __shared__ float slope[2];
    const int b = blockIdx.y;
    const int Ct = C1 + C2;
    for (int i = threadIdx.x; i < Ct * 52; i += blockDim.x) {
        int oc = i / 52, c = i - oc * 52;
        float v = 0.f;
        if (c < NC) v = (oc < C1) ? W1[oc * NC + c] : W2[(oc - C1) * NC + c];
        w[i] = v;
    }
    for (int i = threadIdx.x; i < Ct; i += blockDim.x)
        bias[i] = (i < C1) ? B1[i] : B2[i - C1];
    if (threadIdx.x == 0) { slope[0] = A1[0]; slope[1] = C2 ? A2[0] : 0.f; }
    __syncthreads();
    int sp = blockIdx.x * blockDim.x + threadIdx.x;
    if (sp >= S) return;
    float xv[NC];
    const float* ip = in + (size_t)b * NC * S + sp;
#pragma unroll
    for (int c = 0; c < NC; c++) xv[c] = ip[(size_t)c * S];
    for (int oc = 0; oc < Ct; oc++) {
        float acc = bias[oc];
        const float* wr = &w[oc * 52];
#pragma unroll
        for (int c = 0; c < NC; c++) acc = fmaf(wr[c], xv[c], acc);
        float sl = (oc < C1) ? slope[0] : slope[1];
        float r = acc >= 0.f ? acc : sl * acc;
        if (oc < C1) out1[((size_t)b * C1 + oc) * S + sp] = r;
        else         out2[((size_t)b * C2 + (oc - C1)) * S + sp] = r;
    }
}

// ===========================================================================
// bicubic pyramid resize (align_corners=True, Keys a=-0.75, border clamp)
// ===========================================================================
__device__ __forceinline__ float cubw(float t)
{
    float at = fabsf(t);
    float w1 = (1.25f * at - 2.25f) * at * at + 1.f;
    float w2 = -0.75f * (((at - 5.f) * at + 8.f) * at - 4.f);
    return at <= 1.f ? w1 : (at < 2.f ? w2 : 0.f);
}

__global__ void k_resize(const float* __restrict__ x)
{
    int s = blockIdx.z;
    int n = c_n[s];
    int idx = blockIdx.x * blockDim.x + threadIdx.x;
    if (idx >= n * n) return;
    int bc = blockIdx.y;
    int oy = idx / n, ox = idx % n;
    float scale = (float)(47.0 / (double)(n - 1));
    float syf = (float)oy * scale, sxf = (float)ox * scale;
    float fy0 = floorf(syf), fx0 = floorf(sxf);
    float fy = syf - fy0, fx = sxf - fx0;
    int iy0 = (int)fy0, ix0 = (int)fx0;
    float wy[4], wx[4];
    int iy[4], ix[4];
#pragma unroll
    for (int d = 0; d < 4; d++) {
        wy[d] = cubw(fy - (float)(d - 1));
        wx[d] = cubw(fx - (float)(d - 1));
        int a1 = iy0 + d - 1; iy[d] = a1 < 0 ? 0 : (a1 > 47 ? 47 : a1);
        int a2 = ix0 + d - 1; ix[d] = a2 < 0 ? 0 : (a2 > 47 ? 47 : a2);
    }
    const float* xp = x + (size_t)bc * NP;
    float acc = 0.f;
#pragma unroll
    for (int u = 0; u < 4; u++) {
        float r = 0.f;
#pragma unroll
        for (int v = 0; v < 4; v++) r = fmaf(wx[v], xp[iy[u] * 48 + ix[v]], r);
        acc = fmaf(wy[u], r, acc);
    }
    g_ref[(size_t)bc * STOT + c_off[s] + idx] = acc;
}

// ===========================================================================
// query patches -> split bf16 A1 (hi, lo, hi), directly from g_mb
// ===========================================================================
__global__ void k_xqs()
{
    int idx = blockIdx.x * blockDim.x + threadIdx.x;
    if (idx >= NB * NP * KS1) return;
    int k = idx & 255;
    int p = (idx >> 8) % NP;
    int b = idx / (KS1 * NP);
    float v = 0.f;
    if (k < 225) {
        int c = k / 9, t = k % 9, di = t / 3, dj = t % 3;
        int y = p / 48, xx = p % 48;
        int sy = y + di - 1, sx = xx + dj - 1;
        if (sy >= 0 && sy < 48 && sx >= 0 && sx < 48)
            v = g_mb[((size_t)b * NCR + c) * NP + sy * 48 + sx];
    }
    __nv_bfloat16 h, l;
    split2(v, h, l);
    __nv_bfloat16* o = g_xqs + ((size_t)b * NP + p) * KP1;
    o[k] = h; o[KS1 + k] = l; o[2 * KS1 + k] = h;
}

// ===========================================================================
// normalized key patches (x10 folded) -> split bf16 B1 (hi, hi, lo)
// ===========================================================================
__global__ void k_wns()
{
    int warp = (blockIdx.x * blockDim.x + threadIdx.x) >> 5;
    int lane = threadIdx.x & 31;
    if (warp >= NB * LPAD) return;
    int b = warp / LPAD;
    int l = warp % LPAD;
    __nv_bfloat16* o = g_wns + ((size_t)b * LPAD + l) * KP1;
    if (l >= STOT) {
        for (int k = lane; k < KS1; k += 32) {
            __nv_bfloat16 z = __float2bfloat16(0.f);
            o[k] = z; o[KS1 + k] = z; o[2 * KS1 + k] = z;
        }
        return;
    }
    int s = scale_of(l);
    int n = c_n[s];
    int ll = l - c_off[s];
    int y = ll / n, xx = ll % n;
    float vals[8];
    float ss = 0.f;
    int i = 0;
    for (int k = lane; k < KS1; k += 32, i++) {
        float v = 0.f;
        if (k < 225) {
            int c = k / 9, t = k % 9, di = t / 3, dj = t % 3;
            int sy = y + di - 1, sx = xx + dj - 1;
            if (sy >= 0 && sy < n && sx >= 0 && sx < n)
                v = g_mall[((size_t)b * NCR + c) * STOT + c_off[s] + sy * n + sx];
        }
        vals[i] = v;
        ss = fmaf(v, v, ss);
    }
#pragma unroll
    for (int oo = 16; oo; oo >>= 1) ss += __shfl_xor_sync(0xffffffffu, ss, oo);
    float sc = 10.f / fmaxf(sqrtf(ss), 1e-4f);
    i = 0;
    for (int k = lane; k < KS1; k += 32, i++) {
        __nv_bfloat16 h, lo;
        split2(vals[i] * sc, h, lo);
        o[k] = h; o[KS1 + k] = h; o[2 * KS1 + k] = lo;
    }
}

// ===========================================================================
// value patches transposed -> split bf16 B2 (hi, hi, lo)
// ===========================================================================
__global__ void k_rawTs()
{
    int idx = blockIdx.x * blockDim.x + threadIdx.x;
    if (idx >= NB * NV * LPAD) return;
    int l = idx % LPAD;
    int n = (idx / LPAD) % NV;
    int b = idx / (LPAD * NV);
    float v = 0.f;
    if (l < STOT && n < 450) {
        int s = scale_of(l);
        int nn = c_n[s];
        int ll = l - c_off[s];
        int y = ll / nn, xx = ll % nn;
        int c = n / 9, t = n % 9, di = t / 3, dj = t % 3;
        int sy = y + di - 1, sx = xx + dj - 1;
        if (sy >= 0 && sy < nn && sx >= 0 && sx < nn)
            v = g_ball[((size_t)b * NC + c) * STOT + c_off[s] + sy * nn + sx];
    }
    __nv_bfloat16 h, lo;
    split2(v, h, lo);
    __nv_bfloat16* o = g_rawTs + ((size_t)b * NV + n) * KP2;
    o[l] = h; o[LPAD + l] = h; o[2 * LPAD + l] = lo;
}

// ===========================================================================
// softmax (deferred normalization): pass1 max, pass2 exp + sum + split write
// of UNNORMALIZED e; 1/sum stored for GEMM2's epilogue.
// ===========================================================================
__global__ void k_softmax2()
{
    int warp = (blockIdx.x * blockDim.x + threadIdx.x) >> 5;
    int lane = threadIdx.x & 31;
    if (warp >= NB * NP) return;
    const float* row = g_sc + (size_t)warp * LPAD;
    float m = -1e30f;
    for (int l = lane; l < STOT; l += 32) m = fmaxf(m, row[l]);
#pragma unroll
    for (int o = 16; o; o >>= 1) m = fmaxf(m, __shfl_xor_sync(0xffffffffu, m, o));
    float sum = 0.f;
    __nv_bfloat16* o = g_attns + (size_t)warp * KP2;
    for (int l = lane; l < LPAD; l += 32) {
        float e = (l < STOT) ? __expf(row[l] - m) : 0.f;
        sum += e;
        __nv_bfloat16 h, lo;
        split2(e, h, lo);
        o[l] = h; o[LPAD + l] = lo; o[2 * LPAD + l] = h;
    }
#pragma unroll
    for (int oo = 16; oo; oo >>= 1) sum += __shfl_xor_sync(0xffffffffu, sum, oo);
    if (lane == 0) g_isum[warp] = 1.f / sum;
}

// ===========================================================================
// bf16 HMMA GEMM: C[M,N] = diag(rowScale) * (A[M,K'] * B[N,K']^T)
// CTA 128x128, BK=64, 8 warps (2x4), warp tile 64x32, m16n8k16 mma
// ===========================================================================
__device__ __forceinline__ void load_tile(uint32_t sdst, const char* gsrc,
                                          size_t ldbytes, int tid)
{
#pragma unroll
    for (int i = 0; i < 4; i++) {
        int u = tid + i * 256;
        int row = u >> 3, seg = u & 7;
        uint32_t off = swz((uint32_t)(row * 128 + seg * 16));
        cpa16(sdst + off, gsrc + (size_t)row * ldbytes + seg * 16);
    }
}

__global__ void __launch_bounds__(256)
k_mma(const __nv_bfloat16* __restrict__ A, const __nv_bfloat16* __restrict__ B,
      float* __restrict__ C, int nch, int lda, int ldb, int ldc,
      size_t sA, size_t sB, size_t sC,
      const float* __restrict__ rowScale, int scaleStride)
{
    extern __shared__ char smem[];
    const uint32_t tile0 = (smem_u32(smem) + 1023u) & ~1023u;
    const int tid = threadIdx.x, wid = tid >> 5, lane = tid & 31;
    const int wm = wid >> 2, wn = wid & 3;

    const char* Abase = (const char*)(A + blockIdx.z * sA + (size_t)blockIdx.y * 128 * lda);
    const char* Bbase = (const char*)(B + blockIdx.z * sB + (size_t)blockIdx.x * 128 * ldb);
    const size_t ldab = (size_t)lda * 2, ldbb = (size_t)ldb * 2;

    float acc[4][4][4];
#pragma unroll
    for (int i = 0; i < 4; i++)
#pragma unroll
        for (int j = 0; j < 4; j++)
#pragma unroll
            for (int r = 0; r < 4; r++) acc[i][j][r] = 0.f;

    const int a_row = wm * 64 + (lane & 15);
    const int a_chk = lane >> 4;
    const int b_row = wn * 32 + ((lane >> 4) << 3) + (lane & 7);
    const int b_chk = (lane >> 3) & 1;

    load_tile(tile0,         Abase, ldab, tid);
    load_tile(tile0 + 16384, Bbase, ldbb, tid);
    cpa_commit();

    for (int c = 0; c < nch; c++) {
        if (c + 1 < nch) {
            uint32_t t1 = tile0 + (uint32_t)((c + 1) & 1) * 32768u;
            load_tile(t1,         Abase + (size_t)(c + 1) * 128, ldab, tid);
            load_tile(t1 + 16384, Bbase + (size_t)(c + 1) * 128, ldbb, tid);
            cpa_commit();
            cpa_wait<1>();
        } else {
            cpa_wait<0>();
        }
        __syncthreads();
        uint32_t sa = tile0 + (uint32_t)(c & 1) * 32768u;
        uint32_t sb = sa + 16384;
#pragma unroll
        for (int kb = 0; kb < 4; kb++) {
            uint32_t af[4][4], bf[4][2];
#pragma unroll
            for (int mi = 0; mi < 4; mi++) {
                uint32_t off = swz((uint32_t)((a_row + mi * 16) * 128 + (kb * 2 + a_chk) * 16));
                ldm_x4(af[mi][0], af[mi][1], af[mi][2], af[mi][3], sa + off);
            }
#pragma unroll
            for (int nj = 0; nj < 2; nj++) {
                uint32_t off = swz((uint32_t)((b_row + nj * 16) * 128 + (kb * 2 + b_chk) * 16));
                uint32_t r0, r1, r2, r3;
                ldm_x4(r0, r1, r2, r3, sb + off);
                bf[nj * 2][0] = r0; bf[nj * 2][1] = r1;
                bf[nj * 2 + 1][0] = r2; bf[nj * 2 + 1][1] = r3;
            }
#pragma unroll
            for (int mi = 0; mi < 4; mi++)
#pragma unroll
                for (int nj = 0; nj < 4; nj++)
                    mma16816(acc[mi][nj], af[mi], bf[nj]);
        }
        __syncthreads();
    }

    float* Cb = C + blockIdx.z * sC;
    const float* rs = rowScale ? rowScale + (size_t)blockIdx.z * scaleStride : nullptr;
    const int m0g = blockIdx.y * 128 + wm * 64;
    const int n0g = blockIdx.x * 128 + wn * 32;
#pragma unroll
    for (int mi = 0; mi < 4; mi++) {
        int r = m0g + mi * 16 + (lane >> 2);
        float s0 = 1.f, s1 = 1.f;
        if (rs) { s0 = rs[r]; s1 = rs[r + 8]; }
#pragma unroll
        for (int nj = 0; nj < 4; nj++) {
            int cc = n0g + nj * 8 + (lane & 3) * 2;
            *(float2*)(Cb + (size_t)r * ldc + cc) =
                make_float2(acc[mi][nj][0] * s0, acc[mi][nj][1] * s0);
            *(float2*)(Cb + (size_t)(r + 8) * ldc + cc) =
                make_float2(acc[mi][nj][2] * s1, acc[mi][nj][3] * s1);
        }
    }
}

// ---------------------------------------------------------------------------
// epilogue: transposed-conv combine of (already-normalized) O + residual
__global__ void k_epi(const float* __restrict__ x, float* __restrict__ out)
{
    int idx = blockIdx.x * blockDim.x + threadIdx.x;
    if (idx >= NB * NC * NP) return;
    int p = idx % NP;
    int c = (idx / NP) % NC;
    int b = idx / (NP * NC);
    int i = p / 48, j = p % 48;
    float acc = 0.f;
#pragma unroll
    for (int u = 0; u < 3; u++)
#pragma unroll
        for (int v = 0; v < 3; v++) {
            int y = i - u + 1, xx = j - v + 1;
            if (y >= 0 && y < 48 && xx >= 0 && xx < 48)
                acc += g_O[((size_t)b * NP + y * 48 + xx) * NV + c * 9 + u * 3 + v];
        }
    out[idx] = x[idx] + 0.25f * acc;
}

// ---------------------------------------------------------------------------
#define MMA_SMEM (65536 + 1024)

extern "C" void kernel_launch(void* const* d_in, const int* in_sizes, int n_in,
                              void* d_out, int out_size)
{
    const float* x    = (const float*)d_in[0];
    const float* W_mb = (const float*)d_in[1];
    const float* b_mb = (const float*)d_in[2];
    const float* a_mb = (const float*)d_in[3];
    const float* W_m  = (const float*)d_in[4];
    const float* b_m  = (const float*)d_in[5];
    const float* a_m  = (const float*)d_in[6];
    const float* W_a  = (const float*)d_in[7];
    const float* b_a  = (const float*)d_in[8];
    const float* a_a  = (const float*)d_in[9];
    float* out = (float*)d_out;

    float* p_mb;   cudaGetSymbolAddress((void**)&p_mb, g_mb);
    float* p_ref;  cudaGetSymbolAddress((void**)&p_ref, g_ref);
    float* p_mall; cudaGetSymbolAddress((void**)&p_mall, g_mall);
    float* p_ball; cudaGetSymbolAddress((void**)&p_ball, g_ball);
    float* p_sc;   cudaGetSymbolAddress((void**)&p_sc, g_sc);
    float* p_O;    cudaGetSymbolAddress((void**)&p_O, g_O);
    float* p_isum; cudaGetSymbolAddress((void**)&p_isum, g_isum);
    __nv_bfloat16* p_xqs;   cudaGetSymbolAddress((void**)&p_xqs, g_xqs);
    __nv_bfloat16* p_wns;   cudaGetSymbolAddress((void**)&p_wns, g_wns);
    __nv_bfloat16* p_attns; cudaGetSymbolAddress((void**)&p_attns, g_attns);
    __nv_bfloat16* p_rawTs; cudaGetSymbolAddress((void**)&p_rawTs, g_rawTs);

    cudaFuncSetAttribute(k_mma, cudaFuncAttributeMaxDynamicSharedMemorySize, MMA_SMEM);

    // 1) match_base conv (x -> g_mb), 25 oc
    k_convs<<<dim3((NP + 127) / 128, NB), 128>>>(
        x, W_mb, b_mb, a_mb, nullptr, nullptr, nullptr, p_mb, NCR, nullptr, 0, NP);
    // 2) pyramid bicubic resize (x -> g_ref)
    k_resize<<<dim3(9, NB * NC, 5), 256>>>(x);
    // 3) fused keys+values convs (g_ref -> g_mall, g_ball), 75 oc one pass
    k_convs<<<dim3((STOT + 127) / 128, NB), 128>>>(
        p_ref, W_m, b_m, a_m, W_a, b_a, a_a, p_mall, NCR, p_ball, NC, STOT);
    // 4) query patches -> split bf16
    k_xqs<<<(NB * NP * KS1 + 255) / 256, 256>>>();
    // 5) normalized key patches -> split bf16
    k_wns<<<(NB * LPAD * 32 + 255) / 256, 256>>>();
    // 6) scores = xq @ wn^T (3-term bf16 split, HMMA)   [ncu profiles this]
    k_mma<<<dim3(LPAD / 128, NP / 128, NB), 256, MMA_SMEM>>>(
        p_xqs, p_wns, p_sc, KP1 / 64, KP1, KP1, LPAD,
        (size_t)NP * KP1, (size_t)LPAD * KP1, (size_t)NP * LPAD, nullptr, 0);
    // 7) value patches -> split bf16 (independent of 6)
    k_rawTs<<<(NB * NV * LPAD + 255) / 256, 256>>>();
    // 8) softmax: max pass + exp/sum pass, writes unnormalized e + 1/sum
    k_softmax2<<<(NB * NP * 32 + 255) / 256, 256>>>();
    // 9) O = diag(1/sum) * (e @ rawT^T)
    k_mma<<<dim3(NV / 128, NP / 128, NB), 256, MMA_SMEM>>>(
        p_attns, p_rawTs, p_O, KP2 / 64, KP2, KP2, NV,
        (size_t)NP * KP2, (size_t)NV * KP2, (size_t)NP * NV, p_isum, NP);
    // 10) transposed-conv combine + residual
    k_epi<<<(NB * NC * NP + 255) / 256, 256>>>(x, out);
}

// round 6
// speedup vs baseline: 1.2147x; 1.2147x over previous
#include <cuda_runtime.h>
#include <cuda_fp16.h>
#include <math.h>
#include <stdint.h>

// Problem constants
#define NB 2          // batch
#define NC 50         // channels
#define NCR 25        // reduced channels
#define NP 2304       // H*W = 48*48
#define STOT 7470     // total pyramid spatial positions (= L)
#define LPAD 7552     // L padded to multiple of 128
#define KS1 256       // per-section K for GEMM1 (fp16 split)
#define KP1 768       // 3*256, GEMM1 split-K total
#define KP2 15104     // 2*7552, GEMM2 split-K total (2-term fp16)
#define NV 512        // 450 value dims padded to 512

__constant__ int c_n[5]   = {48, 43, 38, 33, 28};
__constant__ int c_off[5] = {0, 2304, 4153, 5597, 6686};

// ---- scratch (static __device__ arrays; no allocations) ----
__device__ float g_ref [(size_t)NB * NC  * STOT];
__device__ float g_mb  [(size_t)NB * NCR * NP];
__device__ float g_mall[(size_t)NB * NCR * STOT];
__device__ float g_ball[(size_t)NB * NC  * STOT];
__device__ float g_sc  [(size_t)NB * NP * LPAD];          // scores (pre-softmax)
__device__ float g_O   [(size_t)NB * NP * NV];            // (attn @ values), normalized
__device__ float g_isum[(size_t)NB * NP];                 // 1/softmax-denominator
__device__ __align__(256) __half g_xqs  [(size_t)NB * NP * KP1];   // A1 (hi,lo,hi)
__device__ __align__(256) __half g_wns  [(size_t)NB * LPAD * KP1]; // B1 (hi,hi,lo)
__device__ __align__(256) __half g_attns[(size_t)NB * NP * KP2];   // A2 (hi,lo)
__device__ __align__(256) __half g_rawTs[(size_t)NB * NV * KP2];   // B2 (hi,hi)

// ===========================================================================
// PTX helpers
// ===========================================================================
__device__ __forceinline__ uint32_t smem_u32(const void* p)
{
    uint32_t a;
    asm("{ .reg .u64 t; cvta.to.shared.u64 t, %1; cvt.u32.u64 %0, t; }" : "=r"(a) : "l"(p));
    return a;
}
__device__ __forceinline__ void cpa16(uint32_t dst, const void* src)
{
    asm volatile("cp.async.cg.shared.global [%0], [%1], 16;" :: "r"(dst), "l"(src));
}
__device__ __forceinline__ void cpa_commit() { asm volatile("cp.async.commit_group;" ::: "memory"); }
template <int N> __device__ __forceinline__ void cpa_wait()
{
    asm volatile("cp.async.wait_group %0;" :: "n"(N) : "memory");
}
__device__ __forceinline__ void ldm_x4(uint32_t& r0, uint32_t& r1, uint32_t& r2, uint32_t& r3,
                                       uint32_t addr)
{
    asm volatile("ldmatrix.sync.aligned.m8n8.x4.shared.b16 {%0,%1,%2,%3}, [%4];"
                 : "=r"(r0), "=r"(r1), "=r"(r2), "=r"(r3) : "r"(addr));
}
__device__ __forceinline__ void mma16816(float* d, const uint32_t* a, const uint32_t* b)
{
    asm volatile("mma.sync.aligned.m16n8k16.row.col.f32.f16.f16.f32 "
                 "{%0,%1,%2,%3}, {%4,%5,%6,%7}, {%8,%9}, {%0,%1,%2,%3};"
                 : "+f"(d[0]), "+f"(d[1]), "+f"(d[2]), "+f"(d[3])
                 : "r"(a[0]), "r"(a[1]), "r"(a[2]), "r"(a[3]), "r"(b[0]), "r"(b[1]));
}
__device__ __forceinline__ uint32_t swz(uint32_t off) { return off ^ ((off >> 3) & 0x70); }

__device__ __forceinline__ void split2(float v, __half& h, __half& l)
{
    h = __float2half(v);
    l = __float2half(v - __half2float(h));
}

__device__ __forceinline__ int scale_of(int l)
{
    int s = 4;
    while (s > 0 && l < c_off[s]) s--;
    return s;
}

// ===========================================================================
// conv1x1 (+PReLU), 5 output channels per thread. grid.y = b * nChunk + chunk.
// Good parallelism AND x-reuse (5 oc per x load).
// ===========================================================================
#define OCPB 5
__global__ void k_convs(const float* __restrict__ in,
                        const float* __restrict__ W1, const float* __restrict__ B1,
                        const float* __restrict__ A1,
                        const float* __restrict__ W2, const float* __restrict__ B2,
                        const float* __restrict__ A2,
                        float* __restrict__ out1, int C1,
                        float* __restrict__ out2, int C2, int S, int nChunk)
{
    __shared__ float w[OCPB * 52];
    __shared__ float bias[OCPB];
    __shared__ float slope[2];
    const int chunk = blockIdx.y % nChunk;
    const int b = blockIdx.y / nChunk;
    const int oc0 = chunk * OCPB;
    for (int i = threadIdx.x; i < OCPB * 52; i += blockDim.x) {
        int j = i / 52, c = i - j * 52;
        int oc = oc0 + j;
        float v = 0.f;
        if (c < NC) v = (oc < C1) ? W1[oc * NC + c] : W2[(oc - C1) * NC + c];
        w[i] = v;
    }
    if (threadIdx.x < OCPB) {
        int oc = oc0 + threadIdx.x;
        bias[threadIdx.x] = (oc < C1) ? B1[oc] : B2[oc - C1];
    }
    if (threadIdx.x == 0) { slope[0] = A1[0]; slope[1] = C2 ? A2[0] : 0.f; }
    __syncthreads();
    int sp = blockIdx.x * blockDim.x + threadIdx.x;
    if (sp >= S) return;
    float xv[NC];
    const float* ip = in + (size_t)b * NC * S + sp;
#pragma unroll
    for (int c = 0; c < NC; c++) xv[c] = ip[(size_t)c * S];
#pragma unroll
    for (int j = 0; j < OCPB; j++) {
        int oc = oc0 + j;
        float acc = bias[j];
        const float* wr = &w[j * 52];
#pragma unroll
        for (int c = 0; c < NC; c++) acc = fmaf(wr[c], xv[c], acc);
        float sl = (oc < C1) ? slope[0] : slope[1];
        float r = acc >= 0.f ? acc : sl * acc;
        if (oc < C1) out1[((size_t)b * C1 + oc) * S + sp] = r;
        else         out2[((size_t)b * C2 + (oc - C1)) * S + sp] = r;
    }
}

// ===========================================================================
// bicubic pyramid resize (align_corners=True, Keys a=-0.75, border clamp)
// ===========================================================================
__device__ __forceinline__ float cubw(float t)
{
    float at = fabsf(t);
    float w1 = (1.25f * at - 2.25f) * at * at + 1.f;
    float w2 = -0.75f * (((at - 5.f) * at + 8.f) * at - 4.f);
    return at <= 1.f ? w1 : (at < 2.f ? w2 : 0.f);
}

__global__ void k_resize(const float* __restrict__ x)
{
    int s = blockIdx.z;
    int n = c_n[s];
    int idx = blockIdx.x * blockDim.x + threadIdx.x;
    if (idx >= n * n) return;
    int bc = blockIdx.y;
    int oy = idx / n, ox = idx % n;
    float scale = (float)(47.0 / (double)(n - 1));
    float syf = (float)oy * scale, sxf = (float)ox * scale;
    float fy0 = floorf(syf), fx0 = floorf(sxf);
    float fy = syf - fy0, fx = sxf - fx0;
    int iy0 = (int)fy0, ix0 = (int)fx0;
    float wy[4], wx[4];
    int iy[4], ix[4];
#pragma unroll
    for (int d = 0; d < 4; d++) {
        wy[d] = cubw(fy - (float)(d - 1));
        wx[d] = cubw(fx - (float)(d - 1));
        int a1 = iy0 + d - 1; iy[d] = a1 < 0 ? 0 : (a1 > 47 ? 47 : a1);
        int a2 = ix0 + d - 1; ix[d] = a2 < 0 ? 0 : (a2 > 47 ? 47 : a2);
    }
    const float* xp = x + (size_t)bc * NP;
    float acc = 0.f;
#pragma unroll
    for (int u = 0; u < 4; u++) {
        float r = 0.f;
#pragma unroll
        for (int v = 0; v < 4; v++) r = fmaf(wx[v], xp[iy[u] * 48 + ix[v]], r);
        acc = fmaf(wy[u], r, acc);
    }
    g_ref[(size_t)bc * STOT + c_off[s] + idx] = acc;
}

// ===========================================================================
// query patches -> split fp16 A1 (hi, lo, hi)
// ===========================================================================
__global__ void k_xqs()
{
    int idx = blockIdx.x * blockDim.x + threadIdx.x;
    if (idx >= NB * NP * KS1) return;
    int k = idx & 255;
    int p = (idx >> 8) % NP;
    int b = idx / (KS1 * NP);
    float v = 0.f;
    if (k < 225) {
        int c = k / 9, t = k % 9, di = t / 3, dj = t % 3;
        int y = p / 48, xx = p % 48;
        int sy = y + di - 1, sx = xx + dj - 1;
        if (sy >= 0 && sy < 48 && sx >= 0 && sx < 48)
            v = g_mb[((size_t)b * NCR + c) * NP + sy * 48 + sx];
    }
    __half h, l;
    split2(v, h, l);
    __half* o = g_xqs + ((size_t)b * NP + p) * KP1;
    o[k] = h; o[KS1 + k] = l; o[2 * KS1 + k] = h;
}

// ===========================================================================
// normalized key patches (x10 folded) -> split fp16 B1 (hi, hi, lo)
// ===========================================================================
__global__ void k_wns()
{
    int warp = (blockIdx.x * blockDim.x + threadIdx.x) >> 5;
    int lane = threadIdx.x & 31;
    if (warp >= NB * LPAD) return;
    int b = warp / LPAD;
    int l = warp % LPAD;
    __half* o = g_wns + ((size_t)b * LPAD + l) * KP1;
    if (l >= STOT) {
        __half z = __float2half(0.f);
        for (int k = lane; k < KS1; k += 32) {
            o[k] = z; o[KS1 + k] = z; o[2 * KS1 + k] = z;
        }
        return;
    }
    int s = scale_of(l);
    int n = c_n[s];
    int ll = l - c_off[s];
    int y = ll / n, xx = ll % n;
    float vals[8];
    float ss = 0.f;
    int i = 0;
    for (int k = lane; k < KS1; k += 32, i++) {
        float v = 0.f;
        if (k < 225) {
            int c = k / 9, t = k % 9, di = t / 3, dj = t % 3;
            int sy = y + di - 1, sx = xx + dj - 1;
            if (sy >= 0 && sy < n && sx >= 0 && sx < n)
                v = g_mall[((size_t)b * NCR + c) * STOT + c_off[s] + sy * n + sx];
        }
        vals[i] = v;
        ss = fmaf(v, v, ss);
    }
#pragma unroll
    for (int oo = 16; oo; oo >>= 1) ss += __shfl_xor_sync(0xffffffffu, ss, oo);
    float sc = 10.f / fmaxf(sqrtf(ss), 1e-4f);
    i = 0;
    for (int k = lane; k < KS1; k += 32, i++) {
        __half h, lo;
        split2(vals[i] * sc, h, lo);
        o[k] = h; o[KS1 + k] = h; o[2 * KS1 + k] = lo;
    }
}

// ===========================================================================
// value patches transposed -> fp16 B2 (hi duplicated in both sections)
// ===========================================================================
__global__ void k_rawTs()
{
    int idx = blockIdx.x * blockDim.x + threadIdx.x;
    if (idx >= NB * NV * LPAD) return;
    int l = idx % LPAD;
    int n = (idx / LPAD) % NV;
    int b = idx / (LPAD * NV);
    float v = 0.f;
    if (l < STOT && n < 450) {
        int s = scale_of(l);
        int nn = c_n[s];
        int ll = l - c_off[s];
        int y = ll / nn, xx = ll % nn;
        int c = n / 9, t = n % 9, di = t / 3, dj = t % 3;
        int sy = y + di - 1, sx = xx + dj - 1;
        if (sy >= 0 && sy < nn && sx >= 0 && sx < nn)
            v = g_ball[((size_t)b * NC + c) * STOT + c_off[s] + sy * nn + sx];
    }
    __half h = __float2half(v);
    __half* o = g_rawTs + ((size_t)b * NV + n) * KP2;
    o[l] = h; o[LPAD + l] = h;
}

// ===========================================================================
// softmax (deferred normalization): unnormalized e split (hi, lo); 1/sum saved
// ===========================================================================
__global__ void k_softmax2()
{
    int warp = (blockIdx.x * blockDim.x + threadIdx.x) >> 5;
    int lane = threadIdx.x & 31;
    if (warp >= NB * NP) return;
    const float* row = g_sc + (size_t)warp * LPAD;
    float m = -1e30f;
    for (int l = lane; l < STOT; l += 32) m = fmaxf(m, row[l]);
#pragma unroll
    for (int o = 16; o; o >>= 1) m = fmaxf(m, __shfl_xor_sync(0xffffffffu, m, o));
    float sum = 0.f;
    __half* o = g_attns + (size_t)warp * KP2;
    for (int l = lane; l < LPAD; l += 32) {
        float e = (l < STOT) ? __expf(row[l] - m) : 0.f;
        sum += e;
        __half h, lo;
        split2(e, h, lo);
        o[l] = h; o[LPAD + l] = lo;
    }
#pragma unroll
    for (int oo = 16; oo; oo >>= 1) sum += __shfl_xor_sync(0xffffffffu, sum, oo);
    if (lane == 0) g_isum[warp] = 1.f / sum;
}

// ===========================================================================
// fp16 HMMA GEMM: C[M,N] = diag(rowScale) * (A[M,K'] * B[N,K']^T)
// CTA 128x128, BK=64, 8 warps (2x4), warp tile 64x32, m16n8k16
// ===========================================================================
__device__ __forceinline__ void load_tile(uint32_t sdst, const char* gsrc,
                                          size_t ldbytes, int tid)
{
#pragma unroll
    for (int i = 0; i < 4; i++) {
        int u = tid + i * 256;
        int row = u >> 3, seg = u & 7;
        uint32_t off = swz((uint32_t)(row * 128 + seg * 16));
        cpa16(sdst + off, gsrc + (size_t)row * ldbytes + seg * 16);
    }
}

__global__ void __launch_bounds__(256)
k_mma(const __half* __restrict__ A, const __half* __restrict__ B,
      float* __restrict__ C, int nch, int lda, int ldb, int ldc,
      size_t sA, size_t sB, size_t sC,
      const float* __restrict__ rowScale, int scaleStride)
{
    extern __shared__ char smem[];
    const uint32_t tile0 = (smem_u32(smem) + 1023u) & ~1023u;
    const int tid = threadIdx.x, wid = tid >> 5, lane = tid & 31;
    const int wm = wid >> 2, wn = wid & 3;

    const char* Abase = (const char*)(A + blockIdx.z * sA + (size_t)blockIdx.y * 128 * lda);
    const char* Bbase = (const char*)(B + blockIdx.z * sB + (size_t)blockIdx.x * 128 * ldb);
    const size_t ldab = (size_t)lda * 2, ldbb = (size_t)ldb * 2;

    float acc[4][4][4];
#pragma unroll
    for (int i = 0; i < 4; i++)
#pragma unroll
        for (int j = 0; j < 4; j++)
#pragma unroll
            for (int r = 0; r < 4; r++) acc[i][j][r] = 0.f;

    const int a_row = wm * 64 + (lane & 15);
    const int a_chk = lane >> 4;
    const int b_row = wn * 32 + ((lane >> 4) << 3) + (lane & 7);
    const int b_chk = (lane >> 3) & 1;

    load_tile(tile0,         Abase, ldab, tid);
    load_tile(tile0 + 16384, Bbase, ldbb, tid);
    cpa_commit();

    for (int c = 0; c < nch; c++) {
        if (c + 1 < nch) {
            uint32_t t1 = tile0 + (uint32_t)((c + 1) & 1) * 32768u;
            load_tile(t1,         Abase + (size_t)(c + 1) * 128, ldab, tid);
            load_tile(t1 + 16384, Bbase + (size_t)(c + 1) * 128, ldbb, tid);
            cpa_commit();
            cpa_wait<1>();
        } else {
            cpa_wait<0>();
        }
        __syncthreads();
        uint32_t sa = tile0 + (uint32_t)(c & 1) * 32768u;
        uint32_t sb = sa + 16384;
#pragma unroll
        for (int kb = 0; kb < 4; kb++) {
            uint32_t af[4][4], bf[4][2];
#pragma unroll
            for (int mi = 0; mi < 4; mi++) {
                uint32_t off = swz((uint32_t)((a_row + mi * 16) * 128 + (kb * 2 + a_chk) * 16));
                ldm_x4(af[mi][0], af[mi][1], af[mi][2], af[mi][3], sa + off);
            }
#pragma unroll
            for (int nj = 0; nj < 2; nj++) {
                uint32_t off = swz((uint32_t)((b_row + nj * 16) * 128 + (kb * 2 + b_chk) * 16));
                uint32_t r0, r1, r2, r3;
                ldm_x4(r0, r1, r2, r3, sb + off);
                bf[nj * 2][0] = r0; bf[nj * 2][1] = r1;
                bf[nj * 2 + 1][0] = r2; bf[nj * 2 + 1][1] = r3;
            }
#pragma unroll
            for (int mi = 0; mi < 4; mi++)
#pragma unroll
                for (int nj = 0; nj < 4; nj++)
                    mma16816(acc[mi][nj], af[mi], bf[nj]);
        }
        __syncthreads();
    }

    float* Cb = C + blockIdx.z * sC;
    const float* rs = rowScale ? rowScale + (size_t)blockIdx.z * scaleStride : nullptr;
    const int m0g = blockIdx.y * 128 + wm * 64;
    const int n0g = blockIdx.x * 128 + wn * 32;
#pragma unroll
    for (int mi = 0; mi < 4; mi++) {
        int r = m0g + mi * 16 + (lane >> 2);
        float s0 = 1.f, s1 = 1.f;
        if (rs) { s0 = rs[r]; s1 = rs[r + 8]; }
#pragma unroll
        for (int nj = 0; nj < 4; nj++) {
            int cc = n0g + nj * 8 + (lane & 3) * 2;
            *(float2*)(Cb + (size_t)r * ldc + cc) =
                make_float2(acc[mi][nj][0] * s0, acc[mi][nj][1] * s0);
            *(float2*)(Cb + (size_t)(r + 8) * ldc + cc) =
                make_float2(acc[mi][nj][2] * s1, acc[mi][nj][3] * s1);
        }
    }
}

// ---------------------------------------------------------------------------
// epilogue: transposed-conv combine of (already-normalized) O + residual
__global__ void k_epi(const float* __restrict__ x, float* __restrict__ out)
{
    int idx = blockIdx.x * blockDim.x + threadIdx.x;
    if (idx >= NB * NC * NP) return;
    int p = idx % NP;
    int c = (idx / NP) % NC;
    int b = idx / (NP * NC);
    int i = p / 48, j = p % 48;
    float acc = 0.f;
#pragma unroll
    for (int u = 0; u < 3; u++)
#pragma unroll
        for (int v = 0; v < 3; v++) {
            int y = i - u + 1, xx = j - v + 1;
            if (y >= 0 && y < 48 && xx >= 0 && xx < 48)
                acc += g_O[((size_t)b * NP + y * 48 + xx) * NV + c * 9 + u * 3 + v];
        }
    out[idx] = x[idx] + 0.25f * acc;
}

// ---------------------------------------------------------------------------
#define MMA_SMEM (65536 + 1024)

extern "C" void kernel_launch(void* const* d_in, const int* in_sizes, int n_in,
                              void* d_out, int out_size)
{
    const float* x    = (const float*)d_in[0];
    const float* W_mb = (const float*)d_in[1];
    const float* b_mb = (const float*)d_in[2];
    const float* a_mb = (const float*)d_in[3];
    const float* W_m  = (const float*)d_in[4];
    const float* b_m  = (const float*)d_in[5];
    const float* a_m  = (const float*)d_in[6];
    const float* W_a  = (const float*)d_in[7];
    const float* b_a  = (const float*)d_in[8];
    const float* a_a  = (const float*)d_in[9];
    float* out = (float*)d_out;

    float* p_mb;   cudaGetSymbolAddress((void**)&p_mb, g_mb);
    float* p_ref;  cudaGetSymbolAddress((void**)&p_ref, g_ref);
    float* p_mall; cudaGetSymbolAddress((void**)&p_mall, g_mall);
    float* p_ball; cudaGetSymbolAddress((void**)&p_ball, g_ball);
    float* p_sc;   cudaGetSymbolAddress((void**)&p_sc, g_sc);
    float* p_O;    cudaGetSymbolAddress((void**)&p_O, g_O);
    float* p_isum; cudaGetSymbolAddress((void**)&p_isum, g_isum);
    __half* p_xqs;   cudaGetSymbolAddress((void**)&p_xqs, g_xqs);
    __half* p_wns;   cudaGetSymbolAddress((void**)&p_wns, g_wns);
    __half* p_attns; cudaGetSymbolAddress((void**)&p_attns, g_attns);
    __half* p_rawTs; cudaGetSymbolAddress((void**)&p_rawTs, g_rawTs);

    cudaFuncSetAttribute(k_mma, cudaFuncAttributeMaxDynamicSharedMemorySize, MMA_SMEM);

    // 1) match_base conv (x -> g_mb), 25 oc in 5 chunks
    k_convs<<<dim3((NP + 255) / 256, NB * 5), 256>>>(
        x, W_mb, b_mb, a_mb, nullptr, nullptr, nullptr, p_mb, NCR, nullptr, 0, NP, 5);
    // 2) pyramid bicubic resize (x -> g_ref)
    k_resize<<<dim3(9, NB * NC, 5), 256>>>(x);
    // 3) fused keys+values convs (g_ref -> g_mall, g_ball), 75 oc in 15 chunks
    k_convs<<<dim3((STOT + 255) / 256, NB * 15), 256>>>(
        p_ref, W_m, b_m, a_m, W_a, b_a, a_a, p_mall, NCR, p_ball, NC, STOT, 15);
    // 4) query patches -> split fp16
    k_xqs<<<(NB * NP * KS1 + 255) / 256, 256>>>();
    // 5) normalized key patches -> split fp16
    k_wns<<<(NB * LPAD * 32 + 255) / 256, 256>>>();
    // 6) scores = xq @ wn^T (3-term fp16 split, HMMA)
    k_mma<<<dim3(LPAD / 128, NP / 128, NB), 256, MMA_SMEM>>>(
        p_xqs, p_wns, p_sc, KP1 / 64, KP1, KP1, LPAD,
        (size_t)NP * KP1, (size_t)LPAD * KP1, (size_t)NP * LPAD, nullptr, 0);
    // 7) value patches -> fp16 (hi, hi)
    k_rawTs<<<(NB * NV * LPAD + 255) / 256, 256>>>();
    // 8) softmax: max pass + exp/sum pass, writes unnormalized e (hi, lo) + 1/sum
    k_softmax2<<<(NB * NP * 32 + 255) / 256, 256>>>();
    // 9) O = diag(1/sum) * (e @ rawT^T)  (2-term fp16 split)
    k_mma<<<dim3(NV / 128, NP / 128, NB), 256, MMA_SMEM>>>(
        p_attns, p_rawTs, p_O, KP2 / 64, KP2, KP2, NV,
        (size_t)NP * KP2, (size_t)NV * KP2, (size_t)NP * NV, p_isum, NP);
    // 10) transposed-conv combine + residual
    k_epi<<<(NB * NC * NP + 255) / 256, 256>>>(x, out);
}

// round 7
// speedup vs baseline: 1.6148x; 1.3294x over previous
#include <cuda_runtime.h>
#include <cuda_fp16.h>
#include <math.h>
#include <stdint.h>

// Problem constants
#define NB 2          // batch
#define NC 50         // channels
#define NCR 25        // reduced channels
#define NP 2304       // H*W = 48*48
#define STOT 7470     // total pyramid spatial positions (= L)
#define LPAD 7552     // L padded to multiple of 128
#define KS1 256       // per-section K for GEMM1
#define KP1 512       // 2*256: A1=(hi,lo), B1=(hi,hi) -> exact a*b_hi
#define KP2 7552      // 1-term GEMM2 (e_hi * v_hi)
#define NV 512        // 450 value dims padded to 512

__constant__ int c_n[5]   = {48, 43, 38, 33, 28};
__constant__ int c_off[5] = {0, 2304, 4153, 5597, 6686};

// ---- scratch (static __device__ arrays; no allocations) ----
__device__ float g_ref [(size_t)NB * NC  * STOT];
__device__ float g_mb  [(size_t)NB * NCR * NP];
__device__ float g_mall[(size_t)NB * NCR * STOT];
__device__ float g_ball[(size_t)NB * NC  * STOT];
__device__ float g_sc  [(size_t)NB * NP * LPAD];          // scores (pre-softmax)
__device__ float g_O   [(size_t)NB * NP * NV];            // (attn @ values), normalized
__device__ float g_isum[(size_t)NB * NP];                 // 1/softmax-denominator
__device__ __align__(256) __half g_xqs  [(size_t)NB * NP * KP1];   // A1 (hi,lo)
__device__ __align__(256) __half g_wns  [(size_t)NB * LPAD * KP1]; // B1 (hi,hi)
__device__ __align__(256) __half g_attns[(size_t)NB * NP * KP2];   // A2 (e_hi)
__device__ __align__(256) __half g_rawTs[(size_t)NB * NV * KP2];   // B2 (v_hi)

// ===========================================================================
// PTX helpers
// ===========================================================================
__device__ __forceinline__ uint32_t smem_u32(const void* p)
{
    uint32_t a;
    asm("{ .reg .u64 t; cvta.to.shared.u64 t, %1; cvt.u32.u64 %0, t; }" : "=r"(a) : "l"(p));
    return a;
}
__device__ __forceinline__ void cpa16(uint32_t dst, const void* src)
{
    asm volatile("cp.async.cg.shared.global [%0], [%1], 16;" :: "r"(dst), "l"(src));
}
__device__ __forceinline__ void cpa_commit() { asm volatile("cp.async.commit_group;" ::: "memory"); }
template <int N> __device__ __forceinline__ void cpa_wait()
{
    asm volatile("cp.async.wait_group %0;" :: "n"(N) : "memory");
}
__device__ __forceinline__ void ldm_x4(uint32_t& r0, uint32_t& r1, uint32_t& r2, uint32_t& r3,
                                       uint32_t addr)
{
    asm volatile("ldmatrix.sync.aligned.m8n8.x4.shared.b16 {%0,%1,%2,%3}, [%4];"
                 : "=r"(r0), "=r"(r1), "=r"(r2), "=r"(r3) : "r"(addr));
}
__device__ __forceinline__ void mma16816(float* d, const uint32_t* a, const uint32_t* b)
{
    asm volatile("mma.sync.aligned.m16n8k16.row.col.f32.f16.f16.f32 "
                 "{%0,%1,%2,%3}, {%4,%5,%6,%7}, {%8,%9}, {%0,%1,%2,%3};"
                 : "+f"(d[0]), "+f"(d[1]), "+f"(d[2]), "+f"(d[3])
                 : "r"(a[0]), "r"(a[1]), "r"(a[2]), "r"(a[3]), "r"(b[0]), "r"(b[1]));
}
__device__ __forceinline__ uint32_t swz(uint32_t off) { return off ^ ((off >> 3) & 0x70); }

__device__ __forceinline__ void split2(float v, __half& h, __half& l)
{
    h = __float2half(v);
    l = __float2half(v - __half2float(h));
}

__device__ __forceinline__ int scale_of(int l)
{
    int s = 4;
    while (s > 0 && l < c_off[s]) s--;
    return s;
}

// ===========================================================================
// conv1x1 (+PReLU), 5 output channels per thread. grid.y = b * nChunk + chunk.
// ===========================================================================
#define OCPB 5
__global__ void k_convs(const float* __restrict__ in,
                        const float* __restrict__ W1, const float* __restrict__ B1,
                        const float* __restrict__ A1,
                        const float* __restrict__ W2, const float* __restrict__ B2,
                        const float* __restrict__ A2,
                        float* __restrict__ out1, int C1,
                        float* __restrict__ out2, int C2, int S, int nChunk)
{
    __shared__ float w[OCPB * 52];
    __shared__ float bias[OCPB];
    __shared__ float slope[2];
    const int chunk = blockIdx.y % nChunk;
    const int b = blockIdx.y / nChunk;
    const int oc0 = chunk * OCPB;
    for (int i = threadIdx.x; i < OCPB * 52; i += blockDim.x) {
        int j = i / 52, c = i - j * 52;
        int oc = oc0 + j;
        float v = 0.f;
        if (c < NC) v = (oc < C1) ? W1[oc * NC + c] : W2[(oc - C1) * NC + c];
        w[i] = v;
    }
    if (threadIdx.x < OCPB) {
        int oc = oc0 + threadIdx.x;
        bias[threadIdx.x] = (oc < C1) ? B1[oc] : B2[oc - C1];
    }
    if (threadIdx.x == 0) { slope[0] = A1[0]; slope[1] = C2 ? A2[0] : 0.f; }
    __syncthreads();
    int sp = blockIdx.x * blockDim.x + threadIdx.x;
    if (sp >= S) return;
    float xv[NC];
    const float* ip = in + (size_t)b * NC * S + sp;
#pragma unroll
    for (int c = 0; c < NC; c++) xv[c] = ip[(size_t)c * S];
#pragma unroll
    for (int j = 0; j < OCPB; j++) {
        int oc = oc0 + j;
        float acc = bias[j];
        const float* wr = &w[j * 52];
#pragma unroll
        for (int c = 0; c < NC; c++) acc = fmaf(wr[c], xv[c], acc);
        float sl = (oc < C1) ? slope[0] : slope[1];
        float r = acc >= 0.f ? acc : sl * acc;
        if (oc < C1) out1[((size_t)b * C1 + oc) * S + sp] = r;
        else         out2[((size_t)b * C2 + (oc - C1)) * S + sp] = r;
    }
}

// ===========================================================================
// bicubic pyramid resize (align_corners=True, Keys a=-0.75, border clamp)
// ===========================================================================
__device__ __forceinline__ float cubw(float t)
{
    float at = fabsf(t);
    float w1 = (1.25f * at - 2.25f) * at * at + 1.f;
    float w2 = -0.75f * (((at - 5.f) * at + 8.f) * at - 4.f);
    return at <= 1.f ? w1 : (at < 2.f ? w2 : 0.f);
}

__global__ void k_resize(const float* __restrict__ x)
{
    int s = blockIdx.z;
    int n = c_n[s];
    int idx = blockIdx.x * blockDim.x + threadIdx.x;
    if (idx >= n * n) return;
    int bc = blockIdx.y;
    int oy = idx / n, ox = idx % n;
    float scale = (float)(47.0 / (double)(n - 1));
    float syf = (float)oy * scale, sxf = (float)ox * scale;
    float fy0 = floorf(syf), fx0 = floorf(sxf);
    float fy = syf - fy0, fx = sxf - fx0;
    int iy0 = (int)fy0, ix0 = (int)fx0;
    float wy[4], wx[4];
    int iy[4], ix[4];
#pragma unroll
    for (int d = 0; d < 4; d++) {
        wy[d] = cubw(fy - (float)(d - 1));
        wx[d] = cubw(fx - (float)(d - 1));
        int a1 = iy0 + d - 1; iy[d] = a1 < 0 ? 0 : (a1 > 47 ? 47 : a1);
        int a2 = ix0 + d - 1; ix[d] = a2 < 0 ? 0 : (a2 > 47 ? 47 : a2);
    }
    const float* xp = x + (size_t)bc * NP;
    float acc = 0.f;
#pragma unroll
    for (int u = 0; u < 4; u++) {
        float r = 0.f;
#pragma unroll
        for (int v = 0; v < 4; v++) r = fmaf(wx[v], xp[iy[u] * 48 + ix[v]], r);
        acc = fmaf(wy[u], r, acc);
    }
    g_ref[(size_t)bc * STOT + c_off[s] + idx] = acc;
}

// ===========================================================================
// query patches -> split fp16 A1 (hi, lo)
// ===========================================================================
__global__ void k_xqs()
{
    int idx = blockIdx.x * blockDim.x + threadIdx.x;
    if (idx >= NB * NP * KS1) return;
    int k = idx & 255;
    int p = (idx >> 8) % NP;
    int b = idx / (KS1 * NP);
    float v = 0.f;
    if (k < 225) {
        int c = k / 9, t = k % 9, di = t / 3, dj = t % 3;
        int y = p / 48, xx = p % 48;
        int sy = y + di - 1, sx = xx + dj - 1;
        if (sy >= 0 && sy < 48 && sx >= 0 && sx < 48)
            v = g_mb[((size_t)b * NCR + c) * NP + sy * 48 + sx];
    }
    __half h, l;
    split2(v, h, l);
    __half* o = g_xqs + ((size_t)b * NP + p) * KP1;
    o[k] = h; o[KS1 + k] = l;
}

// ===========================================================================
// normalized key patches (x10 folded) -> fp16 B1 (hi duplicated)
// ===========================================================================
__global__ void k_wns()
{
    int warp = (blockIdx.x * blockDim.x + threadIdx.x) >> 5;
    int lane = threadIdx.x & 31;
    if (warp >= NB * LPAD) return;
    int b = warp / LPAD;
    int l = warp % LPAD;
    __half* o = g_wns + ((size_t)b * LPAD + l) * KP1;
    if (l >= STOT) {
        __half z = __float2half(0.f);
        for (int k = lane; k < KS1; k += 32) { o[k] = z; o[KS1 + k] = z; }
        return;
    }
    int s = scale_of(l);
    int n = c_n[s];
    int ll = l - c_off[s];
    int y = ll / n, xx = ll % n;
    float vals[8];
    float ss = 0.f;
    int i = 0;
    for (int k = lane; k < KS1; k += 32, i++) {
        float v = 0.f;
        if (k < 225) {
            int c = k / 9, t = k % 9, di = t / 3, dj = t % 3;
            int sy = y + di - 1, sx = xx + dj - 1;
            if (sy >= 0 && sy < n && sx >= 0 && sx < n)
                v = g_mall[((size_t)b * NCR + c) * STOT + c_off[s] + sy * n + sx];
        }
        vals[i] = v;
        ss = fmaf(v, v, ss);
    }
#pragma unroll
    for (int oo = 16; oo; oo >>= 1) ss += __shfl_xor_sync(0xffffffffu, ss, oo);
    float sc = 10.f / fmaxf(sqrtf(ss), 1e-4f);
    i = 0;
    for (int k = lane; k < KS1; k += 32, i++) {
        __half h = __float2half(vals[i] * sc);
        o[k] = h; o[KS1 + k] = h;
    }
}

// ===========================================================================
// value patches transposed -> fp16 B2 (single copy)
// ===========================================================================
__global__ void k_rawTs()
{
    int idx = blockIdx.x * blockDim.x + threadIdx.x;
    if (idx >= NB * NV * LPAD) return;
    int l = idx % LPAD;
    int n = (idx / LPAD) % NV;
    int b = idx / (LPAD * NV);
    float v = 0.f;
    if (l < STOT && n < 450) {
        int s = scale_of(l);
        int nn = c_n[s];
        int ll = l - c_off[s];
        int y = ll / nn, xx = ll % nn;
        int c = n / 9, t = n % 9, di = t / 3, dj = t % 3;
        int sy = y + di - 1, sx = xx + dj - 1;
        if (sy >= 0 && sy < nn && sx >= 0 && sx < nn)
            v = g_ball[((size_t)b * NC + c) * STOT + c_off[s] + sy * nn + sx];
    }
    g_rawTs[((size_t)b * NV + n) * KP2 + l] = __float2half(v);
}

// ===========================================================================
// softmax (deferred normalization): unnormalized e (hi only); 1/sum saved
// ===========================================================================
__global__ void k_softmax2()
{
    int warp = (blockIdx.x * blockDim.x + threadIdx.x) >> 5;
    int lane = threadIdx.x & 31;
    if (warp >= NB * NP) return;
    const float* row = g_sc + (size_t)warp * LPAD;
    float m = -1e30f;
    for (int l = lane; l < STOT; l += 32) m = fmaxf(m, row[l]);
#pragma unroll
    for (int o = 16; o; o >>= 1) m = fmaxf(m, __shfl_xor_sync(0xffffffffu, m, o));
    float sum = 0.f;
    __half* o = g_attns + (size_t)warp * KP2;
    for (int l = lane; l < LPAD; l += 32) {
        float e = (l < STOT) ? __expf(row[l] - m) : 0.f;
        sum += e;
        o[l] = __float2half(e);
    }
#pragma unroll
    for (int oo = 16; oo; oo >>= 1) sum += __shfl_xor_sync(0xffffffffu, sum, oo);
    if (lane == 0) g_isum[warp] = 1.f / sum;
}

// ===========================================================================
// fp16 HMMA GEMM: C[M,N] = diag(rowScale) * (A[M,K'] * B[N,K']^T)
// CTA 128x128, BK=64, 8 warps (2x4), warp tile 64x32, m16n8k16
// ===========================================================================
__device__ __forceinline__ void load_tile(uint32_t sdst, const char* gsrc,
                                          size_t ldbytes, int tid)
{
#pragma unroll
    for (int i = 0; i < 4; i++) {
        int u = tid + i * 256;
        int row = u >> 3, seg = u & 7;
        uint32_t off = swz((uint32_t)(row * 128 + seg * 16));
        cpa16(sdst + off, gsrc + (size_t)row * ldbytes + seg * 16);
    }
}

__global__ void __launch_bounds__(256)
k_mma(const __half* __restrict__ A, const __half* __restrict__ B,
      float* __restrict__ C, int nch, int lda, int ldb, int ldc,
      size_t sA, size_t sB, size_t sC,
      const float* __restrict__ rowScale, int scaleStride)
{
    extern __shared__ char smem[];
    const uint32_t tile0 = (smem_u32(smem) + 1023u) & ~1023u;
    const int tid = threadIdx.x, wid = tid >> 5, lane = tid & 31;
    const int wm = wid >> 2, wn = wid & 3;

    const char* Abase = (const char*)(A + blockIdx.z * sA + (size_t)blockIdx.y * 128 * lda);
    const char* Bbase = (const char*)(B + blockIdx.z * sB + (size_t)blockIdx.x * 128 * ldb);
    const size_t ldab = (size_t)lda * 2, ldbb = (size_t)ldb * 2;

    float acc[4][4][4];
#pragma unroll
    for (int i = 0; i < 4; i++)
#pragma unroll
        for (int j = 0; j < 4; j++)
#pragma unroll
            for (int r = 0; r < 4; r++) acc[i][j][r] = 0.f;

    const int a_row = wm * 64 + (lane & 15);
    const int a_chk = lane >> 4;
    const int b_row = wn * 32 + ((lane >> 4) << 3) + (lane & 7);
    const int b_chk = (lane >> 3) & 1;

    load_tile(tile0,         Abase, ldab, tid);
    load_tile(tile0 + 16384, Bbase, ldbb, tid);
    cpa_commit();

    for (int c = 0; c < nch; c++) {
        if (c + 1 < nch) {
            uint32_t t1 = tile0 + (uint32_t)((c + 1) & 1) * 32768u;
            load_tile(t1,         Abase + (size_t)(c + 1) * 128, ldab, tid);
            load_tile(t1 + 16384, Bbase + (size_t)(c + 1) * 128, ldbb, tid);
            cpa_commit();
            cpa_wait<1>();
        } else {
            cpa_wait<0>();
        }
        __syncthreads();
        uint32_t sa = tile0 + (uint32_t)(c & 1) * 32768u;
        uint32_t sb = sa + 16384;
#pragma unroll
        for (int kb = 0; kb < 4; kb++) {
            uint32_t af[4][4], bf[4][2];
#pragma unroll
            for (int mi = 0; mi < 4; mi++) {
                uint32_t off = swz((uint32_t)((a_row + mi * 16) * 128 + (kb * 2 + a_chk) * 16));
                ldm_x4(af[mi][0], af[mi][1], af[mi][2], af[mi][3], sa + off);
            }
#pragma unroll
            for (int nj = 0; nj < 2; nj++) {
                uint32_t off = swz((uint32_t)((b_row + nj * 16) * 128 + (kb * 2 + b_chk) * 16));
                uint32_t r0, r1, r2, r3;
                ldm_x4(r0, r1, r2, r3, sb + off);
                bf[nj * 2][0] = r0; bf[nj * 2][1] = r1;
                bf[nj * 2 + 1][0] = r2; bf[nj * 2 + 1][1] = r3;
            }
#pragma unroll
            for (int mi = 0; mi < 4; mi++)
#pragma unroll
                for (int nj = 0; nj < 4; nj++)
                    mma16816(acc[mi][nj], af[mi], bf[nj]);
        }
        __syncthreads();
    }

    float* Cb = C + blockIdx.z * sC;
    const float* rs = rowScale ? rowScale + (size_t)blockIdx.z * scaleStride : nullptr;
    const int m0g = blockIdx.y * 128 + wm * 64;
    const int n0g = blockIdx.x * 128 + wn * 32;
#pragma unroll
    for (int mi = 0; mi < 4; mi++) {
        int r = m0g + mi * 16 + (lane >> 2);
        float s0 = 1.f, s1 = 1.f;
        if (rs) { s0 = rs[r]; s1 = rs[r + 8]; }
#pragma unroll
        for (int nj = 0; nj < 4; nj++) {
            int cc = n0g + nj * 8 + (lane & 3) * 2;
            *(float2*)(Cb + (size_t)r * ldc + cc) =
                make_float2(acc[mi][nj][0] * s0, acc[mi][nj][1] * s0);
            *(float2*)(Cb + (size_t)(r + 8) * ldc + cc) =
                make_float2(acc[mi][nj][2] * s1, acc[mi][nj][3] * s1);
        }
    }
}

// ---------------------------------------------------------------------------
// epilogue: transposed-conv combine of (already-normalized) O + residual
__global__ void k_epi(const float* __restrict__ x, float* __restrict__ out)
{
    int idx = blockIdx.x * blockDim.x + threadIdx.x;
    if (idx >= NB * NC * NP) return;
    int p = idx % NP;
    int c = (idx / NP) % NC;
    int b = idx / (NP * NC);
    int i = p / 48, j = p % 48;
    float acc = 0.f;
#pragma unroll
    for (int u = 0; u < 3; u++)
#pragma unroll
        for (int v = 0; v < 3; v++) {
            int y = i - u + 1, xx = j - v + 1;
            if (y >= 0 && y < 48 && xx >= 0 && xx < 48)
                acc += g_O[((size_t)b * NP + y * 48 + xx) * NV + c * 9 + u * 3 + v];
        }
    out[idx] = x[idx] + 0.25f * acc;
}

// ---------------------------------------------------------------------------
#define MMA_SMEM (65536 + 1024)

extern "C" void kernel_launch(void* const* d_in, const int* in_sizes, int n_in,
                              void* d_out, int out_size)
{
    const float* x    = (const float*)d_in[0];
    const float* W_mb = (const float*)d_in[1];
    const float* b_mb = (const float*)d_in[2];
    const float* a_mb = (const float*)d_in[3];
    const float* W_m  = (const float*)d_in[4];
    const float* b_m  = (const float*)d_in[5];
    const float* a_m  = (const float*)d_in[6];
    const float* W_a  = (const float*)d_in[7];
    const float* b_a  = (const float*)d_in[8];
    const float* a_a  = (const float*)d_in[9];
    float* out = (float*)d_out;

    float* p_mb;   cudaGetSymbolAddress((void**)&p_mb, g_mb);
    float* p_ref;  cudaGetSymbolAddress((void**)&p_ref, g_ref);
    float* p_mall; cudaGetSymbolAddress((void**)&p_mall, g_mall);
    float* p_ball; cudaGetSymbolAddress((void**)&p_ball, g_ball);
    float* p_sc;   cudaGetSymbolAddress((void**)&p_sc, g_sc);
    float* p_O;    cudaGetSymbolAddress((void**)&p_O, g_O);
    float* p_isum; cudaGetSymbolAddress((void**)&p_isum, g_isum);
    __half* p_xqs;   cudaGetSymbolAddress((void**)&p_xqs, g_xqs);
    __half* p_wns;   cudaGetSymbolAddress((void**)&p_wns, g_wns);
    __half* p_attns; cudaGetSymbolAddress((void**)&p_attns, g_attns);
    __half* p_rawTs; cudaGetSymbolAddress((void**)&p_rawTs, g_rawTs);

    cudaFuncSetAttribute(k_mma, cudaFuncAttributeMaxDynamicSharedMemorySize, MMA_SMEM);

    // 1) match_base conv (x -> g_mb), 25 oc in 5 chunks
    k_convs<<<dim3((NP + 255) / 256, NB * 5), 256>>>(
        x, W_mb, b_mb, a_mb, nullptr, nullptr, nullptr, p_mb, NCR, nullptr, 0, NP, 5);
    // 2) pyramid bicubic resize (x -> g_ref)
    k_resize<<<dim3(9, NB * NC, 5), 256>>>(x);
    // 3) fused keys+values convs (g_ref -> g_mall, g_ball), 75 oc in 15 chunks
    k_convs<<<dim3((STOT + 255) / 256, NB * 15), 256>>>(
        p_ref, W_m, b_m, a_m, W_a, b_a, a_a, p_mall, NCR, p_ball, NC, STOT, 15);
    // 4) query patches -> split fp16 (hi, lo)
    k_xqs<<<(NB * NP * KS1 + 255) / 256, 256>>>();
    // 5) normalized key patches -> fp16 (hi, hi)
    k_wns<<<(NB * LPAD * 32 + 255) / 256, 256>>>();
    // 6) scores = xq @ wn_hi^T exactly (2-term fp16, HMMA)
    k_mma<<<dim3(LPAD / 128, NP / 128, NB), 256, MMA_SMEM>>>(
        p_xqs, p_wns, p_sc, KP1 / 64, KP1, KP1, LPAD,
        (size_t)NP * KP1, (size_t)LPAD * KP1, (size_t)NP * LPAD, nullptr, 0);
    // 7) value patches -> fp16 (single)
    k_rawTs<<<(NB * NV * LPAD + 255) / 256, 256>>>();
    // 8) softmax: max pass + exp/sum pass, writes unnormalized e_hi + 1/sum
    k_softmax2<<<(NB * NP * 32 + 255) / 256, 256>>>();
    // 9) O = diag(1/sum) * (e_hi @ v_hi^T)  (1-term fp16)
    k_mma<<<dim3(NV / 128, NP / 128, NB), 256, MMA_SMEM>>>(
        p_attns, p_rawTs, p_O, KP2 / 64, KP2, KP2, NV,
        (size_t)NP * KP2, (size_t)NV * KP2, (size_t)NP * NV, p_isum, NP);
    // 10) transposed-conv combine + residual
    k_epi<<<(NB * NC * NP + 255) / 256, 256>>>(x, out);
}

// round 8
// speedup vs baseline: 1.8529x; 1.1474x over previous
#include <cuda_runtime.h>
#include <cuda_fp16.h>
#include <math.h>
#include <stdint.h>

// Problem constants
#define NB 2          // batch
#define NC 50         // channels
#define NCR 25        // reduced channels
#define NP 2304       // H*W = 48*48
#define STOT 7470     // total pyramid spatial positions (= L)
#define LPAD 7552     // L padded to multiple of 128
#define NT1 (LPAD / 128)   // 59 score tiles per row
#define KP1 256       // 1-term GEMM1 (xq_hi * wn_hi)
#define KP2 7552      // 1-term GEMM2 (e_hi * v_hi)
#define NV 512        // 450 value dims padded to 512

__constant__ int c_n[5]   = {48, 43, 38, 33, 28};
__constant__ int c_off[5] = {0, 2304, 4153, 5597, 6686};

// ---- scratch (static __device__ arrays; no allocations) ----
__device__ float g_ref [(size_t)NB * NC  * STOT];
__device__ float g_mb  [(size_t)NB * NCR * NP];
__device__ float g_mall[(size_t)NB * NCR * STOT];
__device__ float g_ball[(size_t)NB * NC  * STOT];
__device__ float g_sc  [(size_t)NB * NP * LPAD];          // scores (pre-softmax)
__device__ float g_tmax[(size_t)NB * NP * NT1];           // per-tile row maxima
__device__ float g_O   [(size_t)NB * NP * NV];            // (attn @ values), normalized
__device__ float g_isum[(size_t)NB * NP];                 // 1/softmax-denominator
__device__ __align__(256) __half g_xqs  [(size_t)NB * NP * KP1];   // A1 (hi)
__device__ __align__(256) __half g_wns  [(size_t)NB * LPAD * KP1]; // B1 (hi)
__device__ __align__(256) __half g_attns[(size_t)NB * NP * KP2];   // A2 (e_hi)
__device__ __align__(256) __half g_rawTs[(size_t)NB * NV * KP2];   // B2 (v_hi)

// ===========================================================================
// PTX helpers
// ===========================================================================
__device__ __forceinline__ uint32_t smem_u32(const void* p)
{
    uint32_t a;
    asm("{ .reg .u64 t; cvta.to.shared.u64 t, %1; cvt.u32.u64 %0, t; }" : "=r"(a) : "l"(p));
    return a;
}
__device__ __forceinline__ void cpa16(uint32_t dst, const void* src)
{
    asm volatile("cp.async.cg.shared.global [%0], [%1], 16;" :: "r"(dst), "l"(src));
}
__device__ __forceinline__ void cpa_commit() { asm volatile("cp.async.commit_group;" ::: "memory"); }
template <int N> __device__ __forceinline__ void cpa_wait()
{
    asm volatile("cp.async.wait_group %0;" :: "n"(N) : "memory");
}
__device__ __forceinline__ void ldm_x4(uint32_t& r0, uint32_t& r1, uint32_t& r2, uint32_t& r3,
                                       uint32_t addr)
{
    asm volatile("ldmatrix.sync.aligned.m8n8.x4.shared.b16 {%0,%1,%2,%3}, [%4];"
                 : "=r"(r0), "=r"(r1), "=r"(r2), "=r"(r3) : "r"(addr));
}
__device__ __forceinline__ void mma16816(float* d, const uint32_t* a, const uint32_t* b)
{
    asm volatile("mma.sync.aligned.m16n8k16.row.col.f32.f16.f16.f32 "
                 "{%0,%1,%2,%3}, {%4,%5,%6,%7}, {%8,%9}, {%0,%1,%2,%3};"
                 : "+f"(d[0]), "+f"(d[1]), "+f"(d[2]), "+f"(d[3])
                 : "r"(a[0]), "r"(a[1]), "r"(a[2]), "r"(a[3]), "r"(b[0]), "r"(b[1]));
}
__device__ __forceinline__ uint32_t swz(uint32_t off) { return off ^ ((off >> 3) & 0x70); }

__device__ __forceinline__ int scale_of(int l)
{
    int s = 4;
    while (s > 0 && l < c_off[s]) s--;
    return s;
}

// ===========================================================================
// conv1x1 (+PReLU), 5 output channels per thread. grid.y = b * nChunk + chunk.
// ===========================================================================
#define OCPB 5
__global__ void k_convs(const float* __restrict__ in,
                        const float* __restrict__ W1, const float* __restrict__ B1,
                        const float* __restrict__ A1,
                        const float* __restrict__ W2, const float* __restrict__ B2,
                        const float* __restrict__ A2,
                        float* __restrict__ out1, int C1,
                        float* __restrict__ out2, int C2, int S, int nChunk)
{
    __shared__ float w[OCPB * 52];
    __shared__ float bias[OCPB];
    __shared__ float slope[2];
    const int chunk = blockIdx.y % nChunk;
    const int b = blockIdx.y / nChunk;
    const int oc0 = chunk * OCPB;
    for (int i = threadIdx.x; i < OCPB * 52; i += blockDim.x) {
        int j = i / 52, c = i - j * 52;
        int oc = oc0 + j;
        float v = 0.f;
        if (c < NC) v = (oc < C1) ? W1[oc * NC + c] : W2[(oc - C1) * NC + c];
        w[i] = v;
    }
    if (threadIdx.x < OCPB) {
        int oc = oc0 + threadIdx.x;
        bias[threadIdx.x] = (oc < C1) ? B1[oc] : B2[oc - C1];
    }
    if (threadIdx.x == 0) { slope[0] = A1[0]; slope[1] = C2 ? A2[0] : 0.f; }
    __syncthreads();
    int sp = blockIdx.x * blockDim.x + threadIdx.x;
    if (sp >= S) return;
    float xv[NC];
    const float* ip = in + (size_t)b * NC * S + sp;
#pragma unroll
    for (int c = 0; c < NC; c++) xv[c] = ip[(size_t)c * S];
#pragma unroll
    for (int j = 0; j < OCPB; j++) {
        int oc = oc0 + j;
        float acc = bias[j];
        const float* wr = &w[j * 52];
#pragma unroll
        for (int c = 0; c < NC; c++) acc = fmaf(wr[c], xv[c], acc);
        float sl = (oc < C1) ? slope[0] : slope[1];
        float r = acc >= 0.f ? acc : sl * acc;
        if (oc < C1) out1[((size_t)b * C1 + oc) * S + sp] = r;
        else         out2[((size_t)b * C2 + (oc - C1)) * S + sp] = r;
    }
}

// ===========================================================================
// bicubic pyramid resize (align_corners=True, Keys a=-0.75, border clamp)
// ===========================================================================
__device__ __forceinline__ float cubw(float t)
{
    float at = fabsf(t);
    float w1 = (1.25f * at - 2.25f) * at * at + 1.f;
    float w2 = -0.75f * (((at - 5.f) * at + 8.f) * at - 4.f);
    return at <= 1.f ? w1 : (at < 2.f ? w2 : 0.f);
}

__global__ void k_resize(const float* __restrict__ x)
{
    int s = blockIdx.z;
    int n = c_n[s];
    int idx = blockIdx.x * blockDim.x + threadIdx.x;
    if (idx >= n * n) return;
    int bc = blockIdx.y;
    int oy = idx / n, ox = idx % n;
    float scale = (float)(47.0 / (double)(n - 1));
    float syf = (float)oy * scale, sxf = (float)ox * scale;
    float fy0 = floorf(syf), fx0 = floorf(sxf);
    float fy = syf - fy0, fx = sxf - fx0;
    int iy0 = (int)fy0, ix0 = (int)fx0;
    float wy[4], wx[4];
    int iy[4], ix[4];
#pragma unroll
    for (int d = 0; d < 4; d++) {
        wy[d] = cubw(fy - (float)(d - 1));
        wx[d] = cubw(fx - (float)(d - 1));
        int a1 = iy0 + d - 1; iy[d] = a1 < 0 ? 0 : (a1 > 47 ? 47 : a1);
        int a2 = ix0 + d - 1; ix[d] = a2 < 0 ? 0 : (a2 > 47 ? 47 : a2);
    }
    const float* xp = x + (size_t)bc * NP;
    float acc = 0.f;
#pragma unroll
    for (int u = 0; u < 4; u++) {
        float r = 0.f;
#pragma unroll
        for (int v = 0; v < 4; v++) r = fmaf(wx[v], xp[iy[u] * 48 + ix[v]], r);
        acc = fmaf(wy[u], r, acc);
    }
    g_ref[(size_t)bc * STOT + c_off[s] + idx] = acc;
}

// ===========================================================================
// query patches -> fp16 A1 (hi only)
// ===========================================================================
__global__ void k_xqs()
{
    int idx = blockIdx.x * blockDim.x + threadIdx.x;
    if (idx >= NB * NP * KP1) return;
    int k = idx & 255;
    int p = (idx >> 8) % NP;
    int b = idx / (KP1 * NP);
    float v = 0.f;
    if (k < 225) {
        int c = k / 9, t = k % 9, di = t / 3, dj = t % 3;
        int y = p / 48, xx = p % 48;
        int sy = y + di - 1, sx = xx + dj - 1;
        if (sy >= 0 && sy < 48 && sx >= 0 && sx < 48)
            v = g_mb[((size_t)b * NCR + c) * NP + sy * 48 + sx];
    }
    g_xqs[idx] = __float2half(v);
}

// ===========================================================================
// normalized key patches (x10 folded) -> fp16 B1 (hi only)
// ===========================================================================
__global__ void k_wns()
{
    int warp = (blockIdx.x * blockDim.x + threadIdx.x) >> 5;
    int lane = threadIdx.x & 31;
    if (warp >= NB * LPAD) return;
    int b = warp / LPAD;
    int l = warp % LPAD;
    __half* o = g_wns + ((size_t)b * LPAD + l) * KP1;
    if (l >= STOT) {
        __half z = __float2half(0.f);
        for (int k = lane; k < KP1; k += 32) o[k] = z;
        return;
    }
    int s = scale_of(l);
    int n = c_n[s];
    int ll = l - c_off[s];
    int y = ll / n, xx = ll % n;
    float vals[8];
    float ss = 0.f;
    int i = 0;
    for (int k = lane; k < KP1; k += 32, i++) {
        float v = 0.f;
        if (k < 225) {
            int c = k / 9, t = k % 9, di = t / 3, dj = t % 3;
            int sy = y + di - 1, sx = xx + dj - 1;
            if (sy >= 0 && sy < n && sx >= 0 && sx < n)
                v = g_mall[((size_t)b * NCR + c) * STOT + c_off[s] + sy * n + sx];
        }
        vals[i] = v;
        ss = fmaf(v, v, ss);
    }
#pragma unroll
    for (int oo = 16; oo; oo >>= 1) ss += __shfl_xor_sync(0xffffffffu, ss, oo);
    float sc = 10.f / fmaxf(sqrtf(ss), 1e-4f);
    i = 0;
    for (int k = lane; k < KP1; k += 32, i++)
        o[k] = __float2half(vals[i] * sc);
}

// ===========================================================================
// value patches transposed -> fp16 B2
// ===========================================================================
__global__ void k_rawTs()
{
    int idx = blockIdx.x * blockDim.x + threadIdx.x;
    if (idx >= NB * NV * LPAD) return;
    int l = idx % LPAD;
    int n = (idx / LPAD) % NV;
    int b = idx / (LPAD * NV);
    float v = 0.f;
    if (l < STOT && n < 450) {
        int s = scale_of(l);
        int nn = c_n[s];
        int ll = l - c_off[s];
        int y = ll / nn, xx = ll % nn;
        int c = n / 9, t = n % 9, di = t / 3, dj = t % 3;
        int sy = y + di - 1, sx = xx + dj - 1;
        if (sy >= 0 && sy < nn && sx >= 0 && sx < nn)
            v = g_ball[((size_t)b * NC + c) * STOT + c_off[s] + sy * nn + sx];
    }
    g_rawTs[((size_t)b * NV + n) * KP2 + l] = __float2half(v);
}

// ===========================================================================
// softmax (deferred normalization): row max from g_tmax (59 tile maxima),
// then ONE streaming pass: e = exp(s - m), sum, write e_hi; save 1/sum.
// Pad-tile scores are exactly 0 so m >= 0 >= no-overflow; shift-invariant.
// ===========================================================================
__global__ void k_softmax2()
{
    int warp = (blockIdx.x * blockDim.x + threadIdx.x) >> 5;
    int lane = threadIdx.x & 31;
    if (warp >= NB * NP) return;
    const float* tm = g_tmax + (size_t)warp * NT1;
    float m = -1e30f;
    for (int t = lane; t < NT1; t += 32) m = fmaxf(m, tm[t]);
#pragma unroll
    for (int o = 16; o; o >>= 1) m = fmaxf(m, __shfl_xor_sync(0xffffffffu, m, o));
    const float* row = g_sc + (size_t)warp * LPAD;
    float sum = 0.f;
    __half* o = g_attns + (size_t)warp * KP2;
    for (int l = lane; l < LPAD; l += 32) {
        float e = (l < STOT) ? __expf(row[l] - m) : 0.f;
        sum += e;
        o[l] = __float2half(e);
    }
#pragma unroll
    for (int oo = 16; oo; oo >>= 1) sum += __shfl_xor_sync(0xffffffffu, sum, oo);
    if (lane == 0) g_isum[warp] = 1.f / sum;
}

// ===========================================================================
// fp16 HMMA GEMM: C[M,N] = diag(rowScale) * (A[M,K'] * B[N,K']^T)
// CTA 128x128, BK=64, 8 warps (2x4), warp tile 64x32, m16n8k16
// Optional per-row tile-max output (for fused softmax max pass).
// ===========================================================================
__device__ __forceinline__ void load_tile(uint32_t sdst, const char* gsrc,
                                          size_t ldbytes, int tid)
{
#pragma unroll
    for (int i = 0; i < 4; i++) {
        int u = tid + i * 256;
        int row = u >> 3, seg = u & 7;
        uint32_t off = swz((uint32_t)(row * 128 + seg * 16));
        cpa16(sdst + off, gsrc + (size_t)row * ldbytes + seg * 16);
    }
}

__global__ void __launch_bounds__(256)
k_mma(const __half* __restrict__ A, const __half* __restrict__ B,
      float* __restrict__ C, int nch, int lda, int ldb, int ldc,
      size_t sA, size_t sB, size_t sC,
      const float* __restrict__ rowScale, int scaleStride,
      float* __restrict__ tileMax, int nTiles)
{
    extern __shared__ char smem[];
    const uint32_t tile0 = (smem_u32(smem) + 1023u) & ~1023u;
    const int tid = threadIdx.x, wid = tid >> 5, lane = tid & 31;
    const int wm = wid >> 2, wn = wid & 3;

    const char* Abase = (const char*)(A + blockIdx.z * sA + (size_t)blockIdx.y * 128 * lda);
    const char* Bbase = (const char*)(B + blockIdx.z * sB + (size_t)blockIdx.x * 128 * ldb);
    const size_t ldab = (size_t)lda * 2, ldbb = (size_t)ldb * 2;

    float acc[4][4][4];
#pragma unroll
    for (int i = 0; i < 4; i++)
#pragma unroll
        for (int j = 0; j < 4; j++)
#pragma unroll
            for (int r = 0; r < 4; r++) acc[i][j][r] = 0.f;

    const int a_row = wm * 64 + (lane & 15);
    const int a_chk = lane >> 4;
    const int b_row = wn * 32 + ((lane >> 4) << 3) + (lane & 7);
    const int b_chk = (lane >> 3) & 1;

    load_tile(tile0,         Abase, ldab, tid);
    load_tile(tile0 + 16384, Bbase, ldbb, tid);
    cpa_commit();

    for (int c = 0; c < nch; c++) {
        if (c + 1 < nch) {
            uint32_t t1 = tile0 + (uint32_t)((c + 1) & 1) * 32768u;
            load_tile(t1,         Abase + (size_t)(c + 1) * 128, ldab, tid);
            load_tile(t1 + 16384, Bbase + (size_t)(c + 1) * 128, ldbb, tid);
            cpa_commit();
            cpa_wait<1>();
        } else {
            cpa_wait<0>();
        }
        __syncthreads();
        uint32_t sa = tile0 + (uint32_t)(c & 1) * 32768u;
        uint32_t sb = sa + 16384;
#pragma unroll
        for (int kb = 0; kb < 4; kb++) {
            uint32_t af[4][4], bf[4][2];
#pragma unroll
            for (int mi = 0; mi < 4; mi++) {
                uint32_t off = swz((uint32_t)((a_row + mi * 16) * 128 + (kb * 2 + a_chk) * 16));
                ldm_x4(af[mi][0], af[mi][1], af[mi][2], af[mi][3], sa + off);
            }
#pragma unroll
            for (int nj = 0; nj < 2; nj++) {
                uint32_t off = swz((uint32_t)((b_row + nj * 16) * 128 + (kb * 2 + b_chk) * 16));
                uint32_t r0, r1, r2, r3;
                ldm_x4(r0, r1, r2, r3, sb + off);
                bf[nj * 2][0] = r0; bf[nj * 2][1] = r1;
                bf[nj * 2 + 1][0] = r2; bf[nj * 2 + 1][1] = r3;
            }
#pragma unroll
            for (int mi = 0; mi < 4; mi++)
#pragma unroll
                for (int nj = 0; nj < 4; nj++)
                    mma16816(acc[mi][nj], af[mi], bf[nj]);
        }
        __syncthreads();
    }

    float* Cb = C + blockIdx.z * sC;
    const float* rs = rowScale ? rowScale + (size_t)blockIdx.z * scaleStride : nullptr;
    const int m0g = blockIdx.y * 128 + wm * 64;
    const int n0g = blockIdx.x * 128 + wn * 32;
#pragma unroll
    for (int mi = 0; mi < 4; mi++) {
        int r = m0g + mi * 16 + (lane >> 2);
        float s0 = 1.f, s1 = 1.f;
        if (rs) { s0 = rs[r]; s1 = rs[r + 8]; }
#pragma unroll
        for (int nj = 0; nj < 4; nj++) {
            int cc = n0g + nj * 8 + (lane & 3) * 2;
            *(float2*)(Cb + (size_t)r * ldc + cc) =
                make_float2(acc[mi][nj][0] * s0, acc[mi][nj][1] * s0);
            *(float2*)(Cb + (size_t)(r + 8) * ldc + cc) =
                make_float2(acc[mi][nj][2] * s1, acc[mi][nj][3] * s1);
        }
    }

    // fused per-row tile-max (reuses smem tile area; all MMA reads done)
    if (tileMax) {
        float* smax = (float*)(size_t)0;  // placeholder (unused)
        (void)smax;
        float* sm = (float*)smem;         // 128 rows x 4 warp-cols
        __syncthreads();
#pragma unroll
        for (int mi = 0; mi < 4; mi++) {
            float mx0 = -1e30f, mx1 = -1e30f;
#pragma unroll
            for (int nj = 0; nj < 4; nj++) {
                mx0 = fmaxf(mx0, fmaxf(acc[mi][nj][0], acc[mi][nj][1]));
                mx1 = fmaxf(mx1, fmaxf(acc[mi][nj][2], acc[mi][nj][3]));
            }
#pragma unroll
            for (int o = 1; o <= 2; o <<= 1) {
                mx0 = fmaxf(mx0, __shfl_xor_sync(0xffffffffu, mx0, o));
                mx1 = fmaxf(mx1, __shfl_xor_sync(0xffffffffu, mx1, o));
            }
            if ((lane & 3) == 0) {
                int rl = wm * 64 + mi * 16 + (lane >> 2);
                sm[rl * 4 + wn] = mx0;
                sm[(rl + 8) * 4 + wn] = mx1;
            }
        }
        __syncthreads();
        if (tid < 128) {
            float m = fmaxf(fmaxf(sm[tid * 4], sm[tid * 4 + 1]),
                            fmaxf(sm[tid * 4 + 2], sm[tid * 4 + 3]));
            int rowg = blockIdx.y * 128 + tid;
            tileMax[((size_t)blockIdx.z * NP + rowg) * nTiles + blockIdx.x] = m;
        }
    }
}

// ---------------------------------------------------------------------------
// epilogue: transposed-conv combine of (already-normalized) O + residual
__global__ void k_epi(const float* __restrict__ x, float* __restrict__ out)
{
    int idx = blockIdx.x * blockDim.x + threadIdx.x;
    if (idx >= NB * NC * NP) return;
    int p = idx % NP;
    int c = (idx / NP) % NC;
    int b = idx / (NP * NC);
    int i = p / 48, j = p % 48;
    float acc = 0.f;
#pragma unroll
    for (int u = 0; u < 3; u++)
#pragma unroll
        for (int v = 0; v < 3; v++) {
            int y = i - u + 1, xx = j - v + 1;
            if (y >= 0 && y < 48 && xx >= 0 && xx < 48)
                acc += g_O[((size_t)b * NP + y * 48 + xx) * NV + c * 9 + u * 3 + v];
        }
    out[idx] = x[idx] + 0.25f * acc;
}

// ---------------------------------------------------------------------------
#define MMA_SMEM (65536 + 1024)

extern "C" void kernel_launch(void* const* d_in, const int* in_sizes, int n_in,
                              void* d_out, int out_size)
{
    const float* x    = (const float*)d_in[0];
    const float* W_mb = (const float*)d_in[1];
    const float* b_mb = (const float*)d_in[2];
    const float* a_mb = (const float*)d_in[3];
    const float* W_m  = (const float*)d_in[4];
    const float* b_m  = (const float*)d_in[5];
    const float* a_m  = (const float*)d_in[6];
    const float* W_a  = (const float*)d_in[7];
    const float* b_a  = (const float*)d_in[8];
    const float* a_a  = (const float*)d_in[9];
    float* out = (float*)d_out;

    float* p_mb;   cudaGetSymbolAddress((void**)&p_mb, g_mb);
    float* p_ref;  cudaGetSymbolAddress((void**)&p_ref, g_ref);
    float* p_mall; cudaGetSymbolAddress((void**)&p_mall, g_mall);
    float* p_ball; cudaGetSymbolAddress((void**)&p_ball, g_ball);
    float* p_sc;   cudaGetSymbolAddress((void**)&p_sc, g_sc);
    float* p_tmax; cudaGetSymbolAddress((void**)&p_tmax, g_tmax);
    float* p_O;    cudaGetSymbolAddress((void**)&p_O, g_O);
    float* p_isum; cudaGetSymbolAddress((void**)&p_isum, g_isum);
    __half* p_xqs;   cudaGetSymbolAddress((void**)&p_xqs, g_xqs);
    __half* p_wns;   cudaGetSymbolAddress((void**)&p_wns, g_wns);
    __half* p_attns; cudaGetSymbolAddress((void**)&p_attns, g_attns);
    __half* p_rawTs; cudaGetSymbolAddress((void**)&p_rawTs, g_rawTs);

    cudaFuncSetAttribute(k_mma, cudaFuncAttributeMaxDynamicSharedMemorySize, MMA_SMEM);

    // 1) match_base conv (x -> g_mb), 25 oc in 5 chunks
    k_convs<<<dim3((NP + 255) / 256, NB * 5), 256>>>(
        x, W_mb, b_mb, a_mb, nullptr, nullptr, nullptr, p_mb, NCR, nullptr, 0, NP, 5);
    // 2) pyramid bicubic resize (x -> g_ref)
    k_resize<<<dim3(9, NB * NC, 5), 256>>>(x);
    // 3) fused keys+values convs (g_ref -> g_mall, g_ball), 75 oc in 15 chunks
    k_convs<<<dim3((STOT + 255) / 256, NB * 15), 256>>>(
        p_ref, W_m, b_m, a_m, W_a, b_a, a_a, p_mall, NCR, p_ball, NC, STOT, 15);
    // 4) query patches -> fp16
    k_xqs<<<(NB * NP * KP1 + 255) / 256, 256>>>();
    // 5) normalized key patches -> fp16
    k_wns<<<(NB * LPAD * 32 + 255) / 256, 256>>>();
    // 6) scores = xq_hi @ wn_hi^T (1-term fp16) + fused per-tile row maxima
    k_mma<<<dim3(LPAD / 128, NP / 128, NB), 256, MMA_SMEM>>>(
        p_xqs, p_wns, p_sc, KP1 / 64, KP1, KP1, LPAD,
        (size_t)NP * KP1, (size_t)LPAD * KP1, (size_t)NP * LPAD,
        nullptr, 0, p_tmax, NT1);
    // 7) value patches -> fp16
    k_rawTs<<<(NB * NV * LPAD + 255) / 256, 256>>>();
    // 8) softmax: single streaming pass using tile maxima
    k_softmax2<<<(NB * NP * 32 + 255) / 256, 256>>>();
    // 9) O = diag(1/sum) * (e_hi @ v_hi^T)
    k_mma<<<dim3(NV / 128, NP / 128, NB), 256, MMA_SMEM>>>(
        p_attns, p_rawTs, p_O, KP2 / 64, KP2, KP2, NV,
        (size_t)NP * KP2, (size_t)NV * KP2, (size_t)NP * NV,
        p_isum, NP, nullptr, 0);
    // 10) transposed-conv combine + residual
    k_epi<<<(NB * NC * NP + 255) / 256, 256>>>(x, out);
}